// round 15
// baseline (speedup 1.0000x reference)
#include <cuda_runtime.h>

// Problem constants (fixed by setup_inputs)
#define B     128
#define NPIX  2048
#define NBINS 1500
#define NBF   250
#define NREP  256
#define TSIM  1250   // len_bins_sim
#define NBLK  40     // ceil(TSIM/32)
#define N1    ((size_t)B * NREP * NBINS)   // start of gensig region in d_out

#define NCW    14    // copy warps per CTA (warps 0..13)
#define CSEG   8     // segments per copy chunk (5 chunks of 8)
#define NCHK   5
#define RHALF  128   // repeats handled per CTA

__device__ __forceinline__ float ftanh(float x) {
    float r; asm("tanh.approx.f32 %0, %1;" : "=f"(r) : "f"(x)); return r;
}

// ---------------------------------------------------------------------------
// ONE kernel, 256 CTAs x 512 threads: TWO CTAs per batch, each redundantly
// running the identical (deterministic) serial chain, each writing its own
// half of the 256 repeats (no cross-CTA synchronization).
//
// R15 change vs R14: output stores use PLAIN write-back stores instead of
// __stcs. Evidence: R4's standalone writer (plain stores) sustained 3.36TB/s;
// every __stcs-based fused kernel has been capped at 2.1-2.4TB/s regardless
// of warp count / chunking / instruction count / SM coverage. Hypothesis:
// the evict-first hint forces eager small-burst L2->DRAM writeback and is
// the rate limiter. This round changes ONLY the cache hint.
//
//   warp 15   : serial chain via tanh identity, 32 steps/iteration
//   warp 14   : pipelined precompute of next block's history-only partials
//   warps 0-13: copy. Init section written immediately; then 5 chunks of 8
//               segments, spans register-resident, broadcast to 128 rows.
//
// Timeline coords: tl[k]=init[k] for k<250, tl[250+t]=spike_t.
// fb_t = sum_{j=0..249} tl[t+j] * f[j].
// For block at T0, lane i (t=T0+i):
//   - taps j in [0, 217-i]   : spikes through block m-2 -> warp-14 precompute
//   - taps j in [218-i,249-i]: block m-1 spikes         -> 32-tap fixup
//   - taps j in [250-i,249]  : in-block spikes          -> serial shfl chain
// ---------------------------------------------------------------------------
__global__ __launch_bounds__(512, 2) void k_all(
    const float* __restrict__ A,    // (128, 2048)
    const float* __restrict__ st,   // (1500,)
    const float* __restrict__ init, // (128, 250)
    const float* __restrict__ sf,   // (2048,)
    const float* __restrict__ tf,   // (250,)
    const float* __restrict__ fbf,  // (250,)
    const float* __restrict__ bias, // (1,)
    float* __restrict__ out)
{
    __shared__ __align__(16) float sh_tl[1504];   // timeline (init + spikes)
    __shared__ __align__(16) float sh_f[288];     // feedback filter, zero-padded
    __shared__ __align__(16) float sh_fq[288];    // 0.25 * filter (chain taps)
    __shared__ __align__(16) float sh_g[1280];    // drive; overwritten w/ gensig
    __shared__ __align__(16) float sh_tc[256];    // timecourse filter
    __shared__ __align__(16) float sh_st[1504];   // stim_time
    __shared__ float red[512];
    __shared__ float sh_pre[2][32];
    __shared__ int   sh_prog;                     // segments produced (0..NBLK)

    int b    = blockIdx.x >> 1;
    int half = blockIdx.x & 1;                    // which 128 repeats we write
    int tid = threadIdx.x;
    int warp = tid >> 5, lane = tid & 31;
    float* outG = out + N1;

    // ------------------------- setup -------------------------
    if (tid == 0) sh_prog = 0;
    if (tid < NBF) {
        sh_f[tid]  = fbf[tid];
        sh_tc[tid] = tf[tid];
        sh_tl[tid] = init[b * NBF + tid];
    } else if (tid < 288) sh_f[tid] = 0.f;
    for (int j = tid; j < NBINS; j += 512) sh_st[j] = st[j];
    {   // spatial dot partials: 512 threads x 1 float4 = 2048 floats exactly
        const float4* row4 = (const float4*)(A + (size_t)b * NPIX);
        const float4* sf4  = (const float4*)sf;
        float4 a = row4[tid], f = sf4[tid];
        red[tid] = a.x*f.x + a.y*f.y + a.z*f.z + a.w*f.w;
    }
    __syncthreads();

    if (tid < 288) sh_fq[tid] = 0.25f * sh_f[tid];
    if (warp == 0) {   // reduce spatial dot
        float r = 0.f;
        #pragma unroll
        for (int k = 0; k < 16; k++) r += red[lane + 32 * k];
        #pragma unroll
        for (int o = 16; o > 0; o >>= 1) r += __shfl_xor_sync(0xffffffffu, r, o);
        if (lane == 0) red[0] = r;
    }
    // correlation: 3 t-values per thread (t = tid, tid+512, tid+1024)
    float corr[3];
    #pragma unroll
    for (int u = 0; u < 3; u++) {
        int t = tid + 512 * u;
        float a0 = 0, a1 = 0, a2 = 0, a3 = 0;
        if (t < TSIM) {
            for (int j = 0; j < 248; j += 4) {
                a0 = fmaf(sh_st[t + j],     sh_tc[j],     a0);
                a1 = fmaf(sh_st[t + j + 1], sh_tc[j + 1], a1);
                a2 = fmaf(sh_st[t + j + 2], sh_tc[j + 2], a2);
                a3 = fmaf(sh_st[t + j + 3], sh_tc[j + 3], a3);
            }
            a0 = fmaf(sh_st[t + 248], sh_tc[248], a0);
            a1 = fmaf(sh_st[t + 249], sh_tc[249], a1);
        }
        corr[u] = (a0 + a1) + (a2 + a3);
    }
    __syncthreads();
    {
        float fs = red[0], bv = bias[0];
        #pragma unroll
        for (int u = 0; u < 3; u++) {
            int t = tid + 512 * u;
            if (t < 1280) sh_g[t] = (t < TSIM) ? fmaf(fs, corr[u], bv) : 0.f;
        }
    }
    __syncthreads();

    // ------------------------- role split -------------------------
    if (warp == 15) {
        // ---------------- serial chain (tanh form) ----------------
        {   // block-0 precompute: all taps from initial history
            int lim = 250 - lane;
            float a0 = 0, a1 = 0, a2 = 0, a3 = 0;
            int j = 0;
            for (; j + 4 <= lim; j += 4) {
                a0 = fmaf(sh_tl[lane + j],     sh_f[j],     a0);
                a1 = fmaf(sh_tl[lane + j + 1], sh_f[j + 1], a1);
                a2 = fmaf(sh_tl[lane + j + 2], sh_f[j + 2], a2);
                a3 = fmaf(sh_tl[lane + j + 3], sh_f[j + 3], a3);
            }
            for (; j < lim; j++) a0 = fmaf(sh_tl[lane + j], sh_f[j], a0);
            sh_pre[0][lane] = (a0 + a1) + (a2 + a3);
        }
        int fchain = 250 - lane;   // chain tap base (sh_fq)
        int ffix   = 218 - lane;   // fixup tap base (sh_f)

        // per-lane constant: C = 0.25 * sum_k F_ik  (zeros pad k >= lane)
        float Ci = 0.f;
        #pragma unroll
        for (int k = 0; k < 32; k++) Ci += sh_fq[fchain + k];

        for (int m = 0; m < NBLK; m++) {
            asm volatile("bar.sync 1, 64;" ::: "memory");  // warps 14+15 only
            int T0 = m * 32, t = T0 + lane;
            float part = sh_pre[m & 1][lane] + sh_g[t];

            if (m > 0) {   // fixup: previous block's 32 spikes
                int base = 250 + T0 - 32;
                float a0 = 0, a1 = 0, a2 = 0, a3 = 0;
                #pragma unroll
                for (int k = 0; k < 32; k += 4) {
                    a0 = fmaf(sh_tl[base + k],     sh_f[ffix + k],     a0);
                    a1 = fmaf(sh_tl[base + k + 1], sh_f[ffix + k + 1], a1);
                    a2 = fmaf(sh_tl[base + k + 2], sh_f[ffix + k + 2], a2);
                    a3 = fmaf(sh_tl[base + k + 3], sh_f[ffix + k + 3], a3);
                }
                part += (a0 + a1) + (a2 + a3);
            }

            // Y = gensig/2 with folded halves: Y = 0.5*part + C.
            // Chain: Y += t_k * (0.25*F_ik); taps zero for k >= lane so each
            // lane's Y freezes at its own step; tl = tanh(final Y).
            float Y = fmaf(0.5f, part, Ci);
            float tl = 0.f;
            #pragma unroll
            for (int k = 0; k < 32; k++) {
                tl = ftanh(Y);
                float s = __shfl_sync(0xffffffffu, tl, k);
                Y = fmaf(s, sh_fq[fchain + k], Y);
            }

            int kmax = TSIM - T0; if (kmax > 32) kmax = 32;
            if (lane < kmax) {
                sh_tl[250 + t] = fmaf(0.5f, tl, 0.5f);   // spike = sigmoid(g)
                sh_g[t] = 2.0f * Y;                      // gensig
            }
            __syncwarp();
            if (lane == 0) { __threadfence_block(); *(volatile int*)&sh_prog = m + 1; }
        }
    } else if (warp == 14) {
        // ---------------- pipelined precompute ----------------
        for (int m = 0; m < NBLK; m++) {
            asm volatile("bar.sync 1, 64;" ::: "memory");
            if (m + 1 < NBLK) {   // block m+1 partials over spikes through m-1
                int T0n = m * 32 + 32;
                int lim = 218 - lane;
                float a0 = 0, a1 = 0, a2 = 0, a3 = 0;
                int j = 0;
                for (; j + 4 <= lim; j += 4) {
                    a0 = fmaf(sh_tl[T0n + lane + j],     sh_f[j],     a0);
                    a1 = fmaf(sh_tl[T0n + lane + j + 1], sh_f[j + 1], a1);
                    a2 = fmaf(sh_tl[T0n + lane + j + 2], sh_f[j + 2], a2);
                    a3 = fmaf(sh_tl[T0n + lane + j + 3], sh_f[j + 3], a3);
                }
                for (; j < lim; j++) a0 = fmaf(sh_tl[T0n + lane + j], sh_f[j], a0);
                sh_pre[(m + 1) & 1][lane] = (a0 + a1) + (a2 + a3);
            }
        }
    } else {
        // --- copy warps 0..13: this CTA's 128 repeats (register-resident) ---
        volatile int* prog = &sh_prog;
        const float2* stl2 = (const float2*)sh_tl;
        const float2* sg2  = (const float2*)sh_g;
        int rbase = b * NREP + half * RHALF;

        // init section FIRST — no dependency on the chain, starts the DRAM
        // drain immediately.
        {
            float2 iv[4];
            #pragma unroll
            for (int u = 0; u < 4; u++) {
                int i = lane + 32 * u;
                if (i < 125) iv[u] = stl2[i];
            }
            for (int r = warp; r < RHALF; r += NCW) {
                float2* dT = (float2*)(out + (size_t)(rbase + r) * NBINS);
                #pragma unroll
                for (int u = 0; u < 4; u++) {
                    int i = lane + 32 * u;
                    if (i < 125) dT[i] = iv[u];
                }
            }
        }

        for (int c = 0; c < NCHK; c++) {
            while (*prog < CSEG * (c + 1)) __nanosleep(64);
            // producer's __threadfence_block before the flag store orders the
            // spike/gensig STS ahead of the flag; no consumer fence needed.

            int tlo = 125 + 128 * c;                   // timeline float2 range
            int thi = tlo + 128; if (thi > 750) thi = 750;
            int glo = 128 * c;                         // gensig float2 range
            int ghi = glo + 128; if (ghi > 625) ghi = 625;

            // load spans into registers ONCE per chunk
            float2 tl_r[4], g_r[4];
            #pragma unroll
            for (int u = 0; u < 4; u++) {
                int i = tlo + lane + 32 * u;
                if (i < thi) tl_r[u] = stl2[i];
            }
            #pragma unroll
            for (int u = 0; u < 4; u++) {
                int i = glo + lane + 32 * u;
                if (i < ghi) g_r[u] = sg2[i];
            }

            // per-row loop: pure stores (plain write-back)
            for (int r = warp; r < RHALF; r += NCW) {
                size_t row = (size_t)(rbase + r);
                float2* dT = (float2*)(out + row * NBINS);
                float2* dG = (float2*)(outG + row * TSIM);
                #pragma unroll
                for (int u = 0; u < 4; u++) {
                    int i = tlo + lane + 32 * u;
                    if (i < thi) dT[i] = tl_r[u];
                }
                #pragma unroll
                for (int u = 0; u < 4; u++) {
                    int i = glo + lane + 32 * u;
                    if (i < ghi) dG[i] = g_r[u];
                }
            }
        }
    }
}

// ---------------------------------------------------------------------------
extern "C" void kernel_launch(void* const* d_in, const int* in_sizes, int n_in,
                              void* d_out, int out_size) {
    const float* A    = (const float*)d_in[0];  // (128, 2048)
    const float* st   = (const float*)d_in[1];  // (1500,)
    const float* init = (const float*)d_in[2];  // (128, 250)
    int off = (n_in >= 8) ? 1 : 0;              // skip n_repeats scalar if present
    const float* sf = (const float*)d_in[3 + off];  // (2048,)
    const float* tf = (const float*)d_in[4 + off];  // (250,)
    const float* fb = (const float*)d_in[5 + off];  // (250,)
    const float* bi = (const float*)d_in[6 + off];  // (1,)

    k_all<<<2 * B, 512>>>(A, st, init, sf, tf, fb, bi, (float*)d_out);
}